// round 13
// baseline (speedup 1.0000x reference)
#include <cuda_runtime.h>
#include <cuda_fp16.h>
#include <math.h>
#include <cstdint>

#define NN 5000
#define NFEAT 512
#define NHID 64
#define NHEADS 8
#define NCLASS 40
#define LRALPHA 0.2f
#define MAXDEG 128

// ---------------- device scratch (no allocations allowed) ----------------
__device__ __half2 d_Whh[NN * 256];           // Wh as half2 [N, 256 pairs]
__device__ __half2 d_h1h[NN * 256];           // h1 (elu) as half2 [N, 256 pairs]
__device__ __half2 d_xh [NN * 256];           // x as half2 [N, 256 pairs]
__device__ __half2 d_Wh2h[NN * 32];           // Wh2 as half2 [N, 32 pairs]
__device__ float d_h2 [NN * NHID];            // [N, 64] tf32
__device__ float d_h3 [NN * 256];             // [N, 256] tf32 (200 used)
__device__ __half d_Bt1h[512 * 512];          // W_h^T  [n=h*64+o][k], fp16
__device__ __half d_Bt2h[64 * 512];           // W_o^T  [n][k], fp16
__device__ float d_Bt3[256 * 64];             // fc1_w^T padded [n][k], tf32
__device__ float d_Bt4[64 * 256];             // fc2_w^T padded [n][k], tf32
__device__ float d_bias3[256];
__device__ float d_bias4[64];
__device__ float d_f1 [NHEADS * NN];
__device__ float d_f2 [NHEADS * NN];
__device__ float d_g1 [NN];
__device__ float d_g2 [NN];
__device__ int   d_nbr[NN * MAXDEG];
__device__ int   d_cnt[NN];

__device__ __forceinline__ float leaky(float t) { return t > 0.f ? t : LRALPHA * t; }
__device__ __forceinline__ float elu1(float t)  { return t > 0.f ? t : expf(t) - 1.f; }
__device__ __forceinline__ uint32_t f2tf32(float f) {
    uint32_t u;
    asm("cvt.rna.tf32.f32 %0, %1;" : "=r"(u) : "f"(f));
    return u;
}
__device__ __forceinline__ void mma_tf32(float* c,
                                         uint32_t a0, uint32_t a1, uint32_t a2, uint32_t a3,
                                         uint32_t b0, uint32_t b1) {
    asm volatile("mma.sync.aligned.m16n8k8.row.col.f32.tf32.tf32.f32 "
                 "{%0,%1,%2,%3}, {%4,%5,%6,%7}, {%8,%9}, {%0,%1,%2,%3};"
                 : "+f"(c[0]), "+f"(c[1]), "+f"(c[2]), "+f"(c[3])
                 : "r"(a0), "r"(a1), "r"(a2), "r"(a3), "r"(b0), "r"(b1));
}
__device__ __forceinline__ void mma_f16(float* c,
                                        uint32_t a0, uint32_t a1, uint32_t a2, uint32_t a3,
                                        uint32_t b0, uint32_t b1) {
    asm volatile("mma.sync.aligned.m16n8k16.row.col.f32.f16.f16.f32 "
                 "{%0,%1,%2,%3}, {%4,%5,%6,%7}, {%8,%9}, {%0,%1,%2,%3};"
                 : "+f"(c[0]), "+f"(c[1]), "+f"(c[2]), "+f"(c[3])
                 : "r"(a0), "r"(a1), "r"(a2), "r"(a3), "r"(b0), "r"(b1));
}
__device__ __forceinline__ void cp16(uint32_t dst, const void* src, bool p) {
    int sz = p ? 16 : 0;
    asm volatile("cp.async.cg.shared.global [%0], [%1], 16, %2;"
                 :: "r"(dst), "l"(src), "r"(sz) : "memory");
}
#define CP_COMMIT() asm volatile("cp.async.commit_group;" ::: "memory")
#define CP_WAIT0()  asm volatile("cp.async.wait_group 0;" ::: "memory")

// ---------------- K0: adjacency -> neighbor lists --------------------------
__global__ void gat_build_csr(const float* __restrict__ adj) {
    int n = blockIdx.x;
    __shared__ int cnt;
    if (threadIdx.x == 0) cnt = 0;
    __syncthreads();
    const float4* row = reinterpret_cast<const float4*>(adj + (size_t)n * NN);
    for (int i = threadIdx.x; i < NN / 4; i += blockDim.x) {
        float4 v = row[i];
        int c = i * 4;
        if (v.x != 0.f) { int p = atomicAdd(&cnt, 1); if (p < MAXDEG) d_nbr[n * MAXDEG + p] = c;     }
        if (v.y != 0.f) { int p = atomicAdd(&cnt, 1); if (p < MAXDEG) d_nbr[n * MAXDEG + p] = c + 1; }
        if (v.z != 0.f) { int p = atomicAdd(&cnt, 1); if (p < MAXDEG) d_nbr[n * MAXDEG + p] = c + 2; }
        if (v.w != 0.f) { int p = atomicAdd(&cnt, 1); if (p < MAXDEG) d_nbr[n * MAXDEG + p] = c + 3; }
    }
    __syncthreads();
    if (threadIdx.x == 0) d_cnt[n] = min(cnt, MAXDEG);
}

// ---------------- merged prep: pack x, W_h, W_o to fp16; fc weights tf32 ---
#define XH_BLOCKS   (NN * NFEAT / 4 / 256)    // 2560
#define BT1H_BLOCKS (512 * 512 / 256)         // 1024
#define BT2H_BLOCKS (64 * 512 / 256)          // 128
#define BT3_BLOCKS  (256 * 64 / 256)          // 64
#define BT4_BLOCKS  (64 * 256 / 256)          // 64
#define PREP_BLOCKS (XH_BLOCKS + BT1H_BLOCKS + BT2H_BLOCKS + BT3_BLOCKS + BT4_BLOCKS + 1)
__global__ void gat_prep(const float* __restrict__ x,
                         const float* __restrict__ W_h, const float* __restrict__ W_o,
                         const float* __restrict__ fc1_w, const float* __restrict__ fc1_b,
                         const float* __restrict__ fc2_w, const float* __restrict__ fc2_b) {
    int b = blockIdx.x, tid = threadIdx.x;
    if (b < XH_BLOCKS) {
        int idx = b * 256 + tid;              // float4 index
        float4 v = reinterpret_cast<const float4*>(x)[idx];
        __half2 h0 = __floats2half2_rn(v.x, v.y);
        __half2 h1 = __floats2half2_rn(v.z, v.w);
        uint2 u;
        u.x = *reinterpret_cast<uint32_t*>(&h0);
        u.y = *reinterpret_cast<uint32_t*>(&h1);
        reinterpret_cast<uint2*>(d_xh)[idx] = u;
    } else if ((b -= XH_BLOCKS) < BT1H_BLOCKS) {
        int idx = b * 256 + tid;
        int n = idx >> 9, k = idx & 511;
        int h = n >> 6, o = n & 63;
        d_Bt1h[idx] = __float2half(W_h[h * NFEAT * NHID + k * NHID + o]);
    } else if ((b -= BT1H_BLOCKS) < BT2H_BLOCKS) {
        int idx = b * 256 + tid;
        int n = idx >> 9, k = idx & 511;
        d_Bt2h[idx] = __float2half(W_o[k * NHID + n]);
    } else if ((b -= BT2H_BLOCKS) < BT3_BLOCKS) {
        int idx = b * 256 + tid;
        int n = idx >> 6, k = idx & 63;
        d_Bt3[idx] = (n < 200) ? __uint_as_float(f2tf32(fc1_w[k * 200 + n])) : 0.f;
    } else if ((b -= BT3_BLOCKS) < BT4_BLOCKS) {
        int idx = b * 256 + tid;
        int n = idx >> 8, k = idx & 255;
        d_Bt4[idx] = (n < 40 && k < 200) ? __uint_as_float(f2tf32(fc2_w[k * 40 + n])) : 0.f;
    } else {
        d_bias3[tid] = (tid < 200) ? fc1_b[tid] : 0.f;
        if (tid < 64) d_bias4[tid] = (tid < 40) ? fc2_b[tid] : 0.f;
    }
}

// ---------------- HMMA GEMM (tf32 k8 or fp16 k16), 64-row tiles ------------
// MODE 0: layer1 Wh  -> half2 store + f1/f2 dots (av = a_h slice)   [FH=1]
// MODE 1: layer2 Wh2 -> half2 store + g1/g2 dots (smem reduce)      [FH=1]
// MODE 2: fc1        -> elu(acc+bias) tf32 store (av = bias3 slice) [FH=0]
// MODE 3: fc2        -> acc+bias store cols<40   (av = bias4)       [FH=0]
#define SPAD 36
template<int NT, int KT, int MODE, int FH>
__global__ void __launch_bounds__(256) gat_mma_gemm(
        const char* __restrict__ A, const char* __restrict__ Bt,
        void* __restrict__ Cout, int M,
        const float* __restrict__ av, float* __restrict__ f1o, float* __restrict__ f2o) {
    constexpr int WNT = NT / 2;
    constexpr int NTI = WNT / 8;
    constexpr int ASZ = (MODE == 0) ? 256 : ((MODE == 3) ? 64 : 128);
    constexpr int AW = 64 * SPAD;
    constexpr int BW = NT * SPAD;
    constexpr int ROWB = KT * 128;          // bytes per logical row (dense)

    extern __shared__ float smemf[];
    float*    s_a   = smemf;
    float*    s_red = smemf + ASZ;          // [2][2][64] for MODE1
    uint32_t* As    = reinterpret_cast<uint32_t*>(s_red + 256);
    uint32_t* Bs    = As + 2 * AW;

    int tid = threadIdx.x, w = tid >> 5, l = tid & 31;
    int m0 = blockIdx.x * 64, n0 = blockIdx.y * NT;
    int wm = w & 3, wn = w >> 2;
    int mbase = wm * 16, nbase = wn * WNT;

    if (tid < ASZ) {
        int off = (MODE == 0) ? blockIdx.y * 256 : ((MODE == 2) ? blockIdx.y * 128 : 0);
        s_a[tid] = av[off + tid];
    }

    float acc[NTI][4];
    #pragma unroll
    for (int j = 0; j < NTI; j++)
        #pragma unroll
        for (int q = 0; q < 4; q++) acc[j][q] = 0.f;

    int lq = l >> 2, lr = l & 3;

    auto issue = [&](int kt, int b) {
        #pragma unroll
        for (int i = 0; i < 2; i++) {
            int f = tid + i * 256;
            int r = f >> 3, c4 = f & 7;
            int m = m0 + r;
            bool p = m < M;
            const char* src = A + (size_t)(p ? m : 0) * ROWB + kt * 128 + c4 * 16;
            cp16((uint32_t)__cvta_generic_to_shared(As + b * AW + r * SPAD + c4 * 4), src, p);
        }
        #pragma unroll
        for (int i = 0; i < NT / 32; i++) {
            int f = tid + i * 256;
            int r = f >> 3, c4 = f & 7;
            const char* src = Bt + (size_t)(n0 + r) * ROWB + kt * 128 + c4 * 16;
            cp16((uint32_t)__cvta_generic_to_shared(Bs + b * BW + r * SPAD + c4 * 4), src, true);
        }
    };

    issue(0, 0);
    CP_COMMIT();

    for (int kt = 0; kt < KT; kt++) {
        if (kt + 1 < KT) {
            issue(kt + 1, (kt + 1) & 1);
            CP_COMMIT();
            asm volatile("cp.async.wait_group 1;" ::: "memory");
        } else {
            CP_WAIT0();
        }
        __syncthreads();

        int b = kt & 1;
        const uint32_t* Ab = As + b * AW;
        const uint32_t* Bb = Bs + b * BW;
        #pragma unroll
        for (int ks = 0; ks < 4; ks++) {
            int kc = ks * 8 + lr;
            const uint32_t* ap = Ab + (mbase + lq) * SPAD;
            uint32_t a0 = ap[kc];
            uint32_t a1 = ap[8 * SPAD + kc];
            uint32_t a2 = ap[kc + 4];
            uint32_t a3 = ap[8 * SPAD + kc + 4];
            #pragma unroll
            for (int nt = 0; nt < NTI; nt++) {
                const uint32_t* bp = Bb + (nbase + nt * 8 + lq) * SPAD;
                uint32_t b0 = bp[kc];
                uint32_t b1 = bp[kc + 4];
                if (FH) mma_f16(acc[nt], a0, a1, a2, a3, b0, b1);
                else    mma_tf32(acc[nt], a0, a1, a2, a3, b0, b1);
            }
        }
        __syncthreads();
    }

    // epilogue stores
    int r0 = m0 + mbase + lq;
    int r1 = r0 + 8;
    #pragma unroll
    for (int nt = 0; nt < NTI; nt++) {
        int lc = nbase + nt * 8 + lr * 2;   // tile-local col
        int c = n0 + lc;                    // global col
        if (MODE == 0) {
            __half2* Ch = reinterpret_cast<__half2*>(Cout);
            if (r0 < M) Ch[(size_t)r0 * 256 + (c >> 1)] =
                __floats2half2_rn(acc[nt][0], acc[nt][1]);
            if (r1 < M) Ch[(size_t)r1 * 256 + (c >> 1)] =
                __floats2half2_rn(acc[nt][2], acc[nt][3]);
        } else if (MODE == 1) {
            __half2* Ch = reinterpret_cast<__half2*>(Cout);
            if (r0 < M) Ch[(size_t)r0 * 32 + (c >> 1)] =
                __floats2half2_rn(acc[nt][0], acc[nt][1]);
            if (r1 < M) Ch[(size_t)r1 * 32 + (c >> 1)] =
                __floats2half2_rn(acc[nt][2], acc[nt][3]);
        } else if (MODE == 2) {
            float* Cf = reinterpret_cast<float*>(Cout);
            float bx = s_a[lc], by = s_a[lc + 1];
            if (r0 < M)
                *reinterpret_cast<float2*>(Cf + (size_t)r0 * 256 + c) = make_float2(
                    __uint_as_float(f2tf32(elu1(acc[nt][0] + bx))),
                    __uint_as_float(f2tf32(elu1(acc[nt][1] + by))));
            if (r1 < M)
                *reinterpret_cast<float2*>(Cf + (size_t)r1 * 256 + c) = make_float2(
                    __uint_as_float(f2tf32(elu1(acc[nt][2] + bx))),
                    __uint_as_float(f2tf32(elu1(acc[nt][3] + by))));
        } else {  // MODE 3
            if (c < NCLASS) {
                float* Cf = reinterpret_cast<float*>(Cout);
                float bx = s_a[c], by = s_a[c + 1];
                if (r0 < M)
                    *reinterpret_cast<float2*>(Cf + (size_t)r0 * NCLASS + c) =
                        make_float2(acc[nt][0] + bx, acc[nt][1] + by);
                if (r1 < M)
                    *reinterpret_cast<float2*>(Cf + (size_t)r1 * NCLASS + c) =
                        make_float2(acc[nt][2] + bx, acc[nt][3] + by);
            }
        }
    }

    // fused attention-vector dots
    if (MODE <= 1) {
        const float* va = (MODE == 0) ? s_a + wn * 128 : s_a;
        float p1a = 0.f, p1b = 0.f, p2a = 0.f, p2b = 0.f;
        #pragma unroll
        for (int nt = 0; nt < NTI; nt++) {
            int o = (MODE == 0) ? (nt * 8 + lr * 2) : (nbase + nt * 8 + lr * 2);
            float a1x = va[o], a1y = va[o + 1];
            float a2x = va[64 + o], a2y = va[64 + o + 1];
            p1a += acc[nt][0] * a1x + acc[nt][1] * a1y;
            p2a += acc[nt][0] * a2x + acc[nt][1] * a2y;
            p1b += acc[nt][2] * a1x + acc[nt][3] * a1y;
            p2b += acc[nt][2] * a2x + acc[nt][3] * a2y;
        }
        p1a += __shfl_xor_sync(0xffffffffu, p1a, 1); p1a += __shfl_xor_sync(0xffffffffu, p1a, 2);
        p1b += __shfl_xor_sync(0xffffffffu, p1b, 1); p1b += __shfl_xor_sync(0xffffffffu, p1b, 2);
        p2a += __shfl_xor_sync(0xffffffffu, p2a, 1); p2a += __shfl_xor_sync(0xffffffffu, p2a, 2);
        p2b += __shfl_xor_sync(0xffffffffu, p2b, 1); p2b += __shfl_xor_sync(0xffffffffu, p2b, 2);
        if (MODE == 0) {
            if (lr == 0) {
                size_t hoff = (size_t)(blockIdx.y * 2 + wn) * NN;
                if (r0 < M) { f1o[hoff + r0] = p1a; f2o[hoff + r0] = p2a; }
                if (r1 < M) { f1o[hoff + r1] = p1b; f2o[hoff + r1] = p2b; }
            }
        } else {
            float* sp1 = s_red;            // [2][64]
            float* sp2 = s_red + 128;      // [2][64]
            if (lr == 0) {
                sp1[wn * 64 + mbase + lq] = p1a;
                sp1[wn * 64 + mbase + lq + 8] = p1b;
                sp2[wn * 64 + mbase + lq] = p2a;
                sp2[wn * 64 + mbase + lq + 8] = p2b;
            }
            __syncthreads();
            if (tid < 64 && m0 + tid < M) {
                f1o[m0 + tid] = sp1[tid] + sp1[64 + tid];
                f2o[m0 + tid] = sp2[tid] + sp2[64 + tid];
            }
        }
    }
}

// ---------------- K3: layer-1 sparse attention + aggregation + elu --------
__global__ void gat_agg1() {
    int n = blockIdx.x;
    __shared__ int   s_idx[MAXDEG];
    __shared__ float s_f2[NHEADS][MAXDEG];
    __shared__ float s_w [NHEADS][MAXDEG];
    int tid = threadIdx.x;
    int deg = d_cnt[n];

    for (int j = tid; j < deg; j += 256) s_idx[j] = d_nbr[n * MAXDEG + j];
    __syncthreads();
    for (int t = tid; t < deg * NHEADS; t += 256) {
        int h = t / deg, j = t - h * deg;
        s_f2[h][j] = d_f2[h * NN + s_idx[j]];
    }
    __syncthreads();

    int w = tid >> 5, lane = tid & 31;
    float f1v = d_f1[w * NN + n];

    float mx = -1e30f;
    for (int j = lane; j < deg; j += 32) mx = fmaxf(mx, leaky(f1v + s_f2[w][j]));
    #pragma unroll
    for (int off = 16; off; off >>= 1) mx = fmaxf(mx, __shfl_xor_sync(0xffffffffu, mx, off));

    float sum = 0.f;
    for (int j = lane; j < deg; j += 32) {
        float e = expf(leaky(f1v + s_f2[w][j]) - mx);
        s_w[w][j] = e;
        sum += e;
    }
    #pragma unroll
    for (int off = 16; off; off >>= 1) sum += __shfl_xor_sync(0xffffffffu, sum, off);
    __syncwarp();

    // aggregation: unroll x4 with batched loads (MLP=4)
    float accx = 0.f, accy = 0.f;
    const __half2* whb = d_Whh + w * 32 + lane;
    int j = 0;
    for (; j + 4 <= deg; j += 4) {
        float w0 = s_w[w][j],     w1 = s_w[w][j + 1];
        float w2 = s_w[w][j + 2], w3 = s_w[w][j + 3];
        __half2 v0 = whb[(size_t)s_idx[j]     * 256];
        __half2 v1 = whb[(size_t)s_idx[j + 1] * 256];
        __half2 v2 = whb[(size_t)s_idx[j + 2] * 256];
        __half2 v3 = whb[(size_t)s_idx[j + 3] * 256];
        float2 f0 = __half22float2(v0), f1 = __half22float2(v1);
        float2 f2 = __half22float2(v2), f3 = __half22float2(v3);
        accx += w0 * f0.x + w1 * f1.x + w2 * f2.x + w3 * f3.x;
        accy += w0 * f0.y + w1 * f1.y + w2 * f2.y + w3 * f3.y;
    }
    for (; j < deg; j++) {
        float wj = s_w[w][j];
        float2 v = __half22float2(whb[(size_t)s_idx[j] * 256]);
        accx += wj * v.x;
        accy += wj * v.y;
    }
    float inv = 1.f / sum;
    d_h1h[(size_t)n * 256 + w * 32 + lane] =
        __floats2half2_rn(elu1(accx * inv), elu1(accy * inv));
}

// ---------------- K6: layer-2 attention + aggregation (h2 only) -----------
__global__ void gat_agg2() {
    int n = blockIdx.x;
    __shared__ int   s_idx[MAXDEG];
    __shared__ float s_g2[MAXDEG];
    __shared__ float s_w [MAXDEG];
    __shared__ float s_sum;
    __shared__ float2 s_part[8][32];
    int tid = threadIdx.x;
    int deg = d_cnt[n];

    for (int j = tid; j < deg; j += 256) {
        int c = d_nbr[n * MAXDEG + j];
        s_idx[j] = c;
        s_g2[j]  = d_g2[c];
    }
    __syncthreads();

    if (tid < 32) {
        float g1n = d_g1[n];
        float mx = -1e30f;
        for (int j = tid; j < deg; j += 32) mx = fmaxf(mx, leaky(g1n + s_g2[j]));
        #pragma unroll
        for (int off = 16; off; off >>= 1) mx = fmaxf(mx, __shfl_xor_sync(0xffffffffu, mx, off));
        float sum = 0.f;
        for (int j = tid; j < deg; j += 32) {
            float e = expf(leaky(g1n + s_g2[j]) - mx);
            s_w[j] = e;
            sum += e;
        }
        #pragma unroll
        for (int off = 16; off; off >>= 1) sum += __shfl_xor_sync(0xffffffffu, sum, off);
        if (tid == 0) s_sum = sum;
    }
    __syncthreads();

    {
        int o2 = tid & 31, part = tid >> 5;
        float ax = 0.f, ay = 0.f;
        for (int j = part; j < deg; j += 8) {
            float wj = s_w[j];
            float2 v = __half22float2(d_Wh2h[(size_t)s_idx[j] * 32 + o2]);
            ax += wj * v.x;
            ay += wj * v.y;
        }
        s_part[part][o2] = make_float2(ax, ay);
    }
    __syncthreads();
    if (tid < 32) {
        float ax = 0.f, ay = 0.f;
        #pragma unroll
        for (int p = 0; p < 8; p++) {
            float2 v = s_part[p][tid];
            ax += v.x;
            ay += v.y;
        }
        float inv = 1.f / s_sum;
        d_h2[(size_t)n * 64 + 2 * tid]     = __uint_as_float(f2tf32(ax * inv));
        d_h2[(size_t)n * 64 + 2 * tid + 1] = __uint_as_float(f2tf32(ay * inv));
    }
}

// ---------------- launch ----------------------------------------------------
extern "C" void kernel_launch(void* const* d_in, const int* in_sizes, int n_in,
                              void* d_out, int out_size) {
    const float* x     = (const float*)d_in[0];
    const float* adj   = (const float*)d_in[1];
    const float* W_h   = (const float*)d_in[2];
    const float* a_h   = (const float*)d_in[3];
    const float* W_o   = (const float*)d_in[4];
    const float* a_o   = (const float*)d_in[5];
    const float* fc1_w = (const float*)d_in[6];
    const float* fc1_b = (const float*)d_in[7];
    const float* fc2_w = (const float*)d_in[8];
    const float* fc2_b = (const float*)d_in[9];
    float* out = (float*)d_out;

    void *pWhh, *pH1h, *pXh, *pWh2h, *pH2, *pH3, *pBt1h, *pBt2h, *pBt3, *pBt4;
    void *pB3, *pB4, *pF1, *pF2, *pG1, *pG2;
    cudaGetSymbolAddress(&pWhh,   d_Whh);
    cudaGetSymbolAddress(&pH1h,   d_h1h);
    cudaGetSymbolAddress(&pXh,    d_xh);
    cudaGetSymbolAddress(&pWh2h,  d_Wh2h);
    cudaGetSymbolAddress(&pH2,    d_h2);
    cudaGetSymbolAddress(&pH3,    d_h3);
    cudaGetSymbolAddress(&pBt1h,  d_Bt1h);
    cudaGetSymbolAddress(&pBt2h,  d_Bt2h);
    cudaGetSymbolAddress(&pBt3,   d_Bt3);
    cudaGetSymbolAddress(&pBt4,   d_Bt4);
    cudaGetSymbolAddress(&pB3,    d_bias3);
    cudaGetSymbolAddress(&pB4,    d_bias4);
    cudaGetSymbolAddress(&pF1,    d_f1);
    cudaGetSymbolAddress(&pF2,    d_f2);
    cudaGetSymbolAddress(&pG1,    d_g1);
    cudaGetSymbolAddress(&pG2,    d_g2);

    const int MB = (NN + 63) / 64;   // 79
    const int SM_M0 = (256 + 256 + (2 * 64 + 2 * 128) * SPAD) * 4;
    const int SM_M1 = (128 + 256 + (2 * 64 + 2 * 64) * SPAD) * 4;
    const int SM_M2 = (128 + 256 + (2 * 64 + 2 * 128) * SPAD) * 4;
    const int SM_M3 = (64 + 256 + (2 * 64 + 2 * 64) * SPAD) * 4;
    cudaFuncSetAttribute(gat_mma_gemm<128, 8, 0, 1>, cudaFuncAttributeMaxDynamicSharedMemorySize, SM_M0);
    cudaFuncSetAttribute(gat_mma_gemm<64, 8, 1, 1>,  cudaFuncAttributeMaxDynamicSharedMemorySize, SM_M1);
    cudaFuncSetAttribute(gat_mma_gemm<128, 2, 2, 0>, cudaFuncAttributeMaxDynamicSharedMemorySize, SM_M2);
    cudaFuncSetAttribute(gat_mma_gemm<64, 8, 3, 0>,  cudaFuncAttributeMaxDynamicSharedMemorySize, SM_M3);

    cudaStream_t s2;
    cudaStreamCreateWithFlags(&s2, cudaStreamNonBlocking);
    cudaEvent_t e0, e1;
    cudaEventCreateWithFlags(&e0, cudaEventDisableTiming);
    cudaEventCreateWithFlags(&e1, cudaEventDisableTiming);

    cudaEventRecord(e0, 0);
    cudaStreamWaitEvent(s2, e0, 0);
    gat_build_csr<<<NN, 256, 0, s2>>>(adj);
    cudaEventRecord(e1, s2);

    gat_prep<<<PREP_BLOCKS, 256>>>(x, W_h, W_o, fc1_w, fc1_b, fc2_w, fc2_b);
    gat_mma_gemm<128, 8, 0, 1><<<dim3(MB, 4), 256, SM_M0>>>((const char*)pXh,
        (const char*)pBt1h, pWhh, NN, a_h, (float*)pF1, (float*)pF2);
    cudaStreamWaitEvent(0, e1, 0);
    gat_agg1<<<NN, 256>>>();
    gat_mma_gemm<64, 8, 1, 1><<<dim3(MB, 1), 256, SM_M1>>>((const char*)pH1h,
        (const char*)pBt2h, pWh2h, NN, a_o, (float*)pG1, (float*)pG2);
    gat_agg2<<<NN, 256>>>();
    gat_mma_gemm<128, 2, 2, 0><<<dim3(MB, 2), 256, SM_M2>>>((const char*)pH2,
        (const char*)pBt3, pH3, NN, (const float*)pB3, nullptr, nullptr);
    gat_mma_gemm<64, 8, 3, 0><<<dim3(MB, 1), 256, SM_M3>>>((const char*)pH3,
        (const char*)pBt4, out, NN, (const float*)pB4, nullptr, nullptr);

    cudaEventDestroy(e0);
    cudaEventDestroy(e1);
    cudaStreamDestroy(s2);
}

// round 14
// speedup vs baseline: 1.0531x; 1.0531x over previous
#include <cuda_runtime.h>
#include <cuda_fp16.h>
#include <math.h>
#include <cstdint>

#define NN 5000
#define NFEAT 512
#define NHID 64
#define NHEADS 8
#define NCLASS 40
#define LRALPHA 0.2f
#define MAXDEG 128

// ---------------- device scratch (no allocations allowed) ----------------
__device__ __half2 d_Whh[NN * 256];           // Wh as half2 [N, 256 pairs]
__device__ __half2 d_h1h[NN * 256];           // h1 (elu) as half2 [N, 256 pairs]
__device__ __half2 d_xh [NN * 256];           // x as half2 [N, 256 pairs]
__device__ __half2 d_Wh2h[NN * 32];           // Wh2 as half2 [N, 32 pairs]
__device__ float d_h2 [NN * NHID];            // [N, 64] tf32
__device__ __half2 d_h3h[NN * 128];           // h3 as half2 [N, 128 pairs] (200 used)
__device__ __half d_Bt1h[512 * 512];          // W_h^T  [n=h*64+o][k], fp16
__device__ __half d_Bt2h[64 * 512];           // W_o^T  [n][k], fp16
__device__ float d_Bt3[256 * 64];             // fc1_w^T padded [n][k], tf32
__device__ __half d_Bt4h[64 * 256];           // fc2_w^T padded [n][k], fp16
__device__ float d_bias3[256];
__device__ float d_bias4[64];
__device__ float d_f1 [NHEADS * NN];
__device__ float d_f2 [NHEADS * NN];
__device__ float d_g1 [NN];
__device__ float d_g2 [NN];
__device__ int   d_nbr[NN * MAXDEG];
__device__ int   d_cnt[NN];

__device__ __forceinline__ float leaky(float t) { return t > 0.f ? t : LRALPHA * t; }
__device__ __forceinline__ float elu1(float t)  { return t > 0.f ? t : expf(t) - 1.f; }
__device__ __forceinline__ uint32_t f2tf32(float f) {
    uint32_t u;
    asm("cvt.rna.tf32.f32 %0, %1;" : "=r"(u) : "f"(f));
    return u;
}
__device__ __forceinline__ void mma_tf32(float* c,
                                         uint32_t a0, uint32_t a1, uint32_t a2, uint32_t a3,
                                         uint32_t b0, uint32_t b1) {
    asm volatile("mma.sync.aligned.m16n8k8.row.col.f32.tf32.tf32.f32 "
                 "{%0,%1,%2,%3}, {%4,%5,%6,%7}, {%8,%9}, {%0,%1,%2,%3};"
                 : "+f"(c[0]), "+f"(c[1]), "+f"(c[2]), "+f"(c[3])
                 : "r"(a0), "r"(a1), "r"(a2), "r"(a3), "r"(b0), "r"(b1));
}
__device__ __forceinline__ void mma_f16(float* c,
                                        uint32_t a0, uint32_t a1, uint32_t a2, uint32_t a3,
                                        uint32_t b0, uint32_t b1) {
    asm volatile("mma.sync.aligned.m16n8k16.row.col.f32.f16.f16.f32 "
                 "{%0,%1,%2,%3}, {%4,%5,%6,%7}, {%8,%9}, {%0,%1,%2,%3};"
                 : "+f"(c[0]), "+f"(c[1]), "+f"(c[2]), "+f"(c[3])
                 : "r"(a0), "r"(a1), "r"(a2), "r"(a3), "r"(b0), "r"(b1));
}
__device__ __forceinline__ void cp16(uint32_t dst, const void* src, bool p) {
    int sz = p ? 16 : 0;
    asm volatile("cp.async.cg.shared.global [%0], [%1], 16, %2;"
                 :: "r"(dst), "l"(src), "r"(sz) : "memory");
}
#define CP_COMMIT() asm volatile("cp.async.commit_group;" ::: "memory")
#define CP_WAIT0()  asm volatile("cp.async.wait_group 0;" ::: "memory")

// ---------------- K0: adjacency -> neighbor lists --------------------------
__global__ void gat_build_csr(const float* __restrict__ adj) {
    int n = blockIdx.x;
    __shared__ int cnt;
    if (threadIdx.x == 0) cnt = 0;
    __syncthreads();
    const float4* row = reinterpret_cast<const float4*>(adj + (size_t)n * NN);
    for (int i = threadIdx.x; i < NN / 4; i += blockDim.x) {
        float4 v = row[i];
        int c = i * 4;
        if (v.x != 0.f) { int p = atomicAdd(&cnt, 1); if (p < MAXDEG) d_nbr[n * MAXDEG + p] = c;     }
        if (v.y != 0.f) { int p = atomicAdd(&cnt, 1); if (p < MAXDEG) d_nbr[n * MAXDEG + p] = c + 1; }
        if (v.z != 0.f) { int p = atomicAdd(&cnt, 1); if (p < MAXDEG) d_nbr[n * MAXDEG + p] = c + 2; }
        if (v.w != 0.f) { int p = atomicAdd(&cnt, 1); if (p < MAXDEG) d_nbr[n * MAXDEG + p] = c + 3; }
    }
    __syncthreads();
    if (threadIdx.x == 0) d_cnt[n] = min(cnt, MAXDEG);
}

// ---------------- merged prep: pack x, W_h, W_o, fc2_w to fp16 -------------
#define XH_BLOCKS   (NN * NFEAT / 4 / 256)    // 2560
#define BT1H_BLOCKS (512 * 512 / 256)         // 1024
#define BT2H_BLOCKS (64 * 512 / 256)          // 128
#define BT3_BLOCKS  (256 * 64 / 256)          // 64
#define BT4_BLOCKS  (64 * 256 / 256)          // 64
#define PREP_BLOCKS (XH_BLOCKS + BT1H_BLOCKS + BT2H_BLOCKS + BT3_BLOCKS + BT4_BLOCKS + 1)
__global__ void gat_prep(const float* __restrict__ x,
                         const float* __restrict__ W_h, const float* __restrict__ W_o,
                         const float* __restrict__ fc1_w, const float* __restrict__ fc1_b,
                         const float* __restrict__ fc2_w, const float* __restrict__ fc2_b) {
    int b = blockIdx.x, tid = threadIdx.x;
    if (b < XH_BLOCKS) {
        int idx = b * 256 + tid;              // float4 index
        float4 v = reinterpret_cast<const float4*>(x)[idx];
        __half2 h0 = __floats2half2_rn(v.x, v.y);
        __half2 h1 = __floats2half2_rn(v.z, v.w);
        uint2 u;
        u.x = *reinterpret_cast<uint32_t*>(&h0);
        u.y = *reinterpret_cast<uint32_t*>(&h1);
        reinterpret_cast<uint2*>(d_xh)[idx] = u;
    } else if ((b -= XH_BLOCKS) < BT1H_BLOCKS) {
        int idx = b * 256 + tid;
        int n = idx >> 9, k = idx & 511;
        int h = n >> 6, o = n & 63;
        d_Bt1h[idx] = __float2half(W_h[h * NFEAT * NHID + k * NHID + o]);
    } else if ((b -= BT1H_BLOCKS) < BT2H_BLOCKS) {
        int idx = b * 256 + tid;
        int n = idx >> 9, k = idx & 511;
        d_Bt2h[idx] = __float2half(W_o[k * NHID + n]);
    } else if ((b -= BT2H_BLOCKS) < BT3_BLOCKS) {
        int idx = b * 256 + tid;
        int n = idx >> 6, k = idx & 63;
        d_Bt3[idx] = (n < 200) ? __uint_as_float(f2tf32(fc1_w[k * 200 + n])) : 0.f;
    } else if ((b -= BT3_BLOCKS) < BT4_BLOCKS) {
        int idx = b * 256 + tid;
        int n = idx >> 8, k = idx & 255;
        d_Bt4h[idx] = (n < 40 && k < 200) ? __float2half(fc2_w[k * 40 + n]) : __float2half(0.f);
    } else {
        d_bias3[tid] = (tid < 200) ? fc1_b[tid] : 0.f;
        if (tid < 64) d_bias4[tid] = (tid < 40) ? fc2_b[tid] : 0.f;
    }
}

// ---------------- HMMA GEMM (tf32 k8 or fp16 k16), 64-row tiles ------------
// MODE 0: layer1 Wh  -> half2 store + f1/f2 dots (av = a_h slice)   [FH=1]
// MODE 1: layer2 Wh2 -> half2 store + g1/g2 dots (smem reduce)      [FH=1]
// MODE 2: fc1        -> elu(acc+bias) half2 store (av = bias3 slice)[FH=0]
// MODE 3: fc2        -> acc+bias store cols<40   (av = bias4)       [FH=1]
#define SPAD 36
template<int NT, int KT, int MODE, int FH>
__global__ void __launch_bounds__(256) gat_mma_gemm(
        const char* __restrict__ A, const char* __restrict__ Bt,
        void* __restrict__ Cout, int M,
        const float* __restrict__ av, float* __restrict__ f1o, float* __restrict__ f2o) {
    constexpr int WNT = NT / 2;
    constexpr int NTI = WNT / 8;
    constexpr int ASZ = (MODE == 0) ? 256 : ((MODE == 3) ? 64 : 128);
    constexpr int AW = 64 * SPAD;
    constexpr int BW = NT * SPAD;
    constexpr int ROWB = KT * 128;          // bytes per logical row (dense)

    extern __shared__ float smemf[];
    float*    s_a   = smemf;
    float*    s_red = smemf + ASZ;          // [2][2][64] for MODE1
    uint32_t* As    = reinterpret_cast<uint32_t*>(s_red + 256);
    uint32_t* Bs    = As + 2 * AW;

    int tid = threadIdx.x, w = tid >> 5, l = tid & 31;
    int m0 = blockIdx.x * 64, n0 = blockIdx.y * NT;
    int wm = w & 3, wn = w >> 2;
    int mbase = wm * 16, nbase = wn * WNT;

    if (tid < ASZ) {
        int off = (MODE == 0) ? blockIdx.y * 256 : ((MODE == 2) ? blockIdx.y * 128 : 0);
        s_a[tid] = av[off + tid];
    }

    float acc[NTI][4];
    #pragma unroll
    for (int j = 0; j < NTI; j++)
        #pragma unroll
        for (int q = 0; q < 4; q++) acc[j][q] = 0.f;

    int lq = l >> 2, lr = l & 3;

    auto issue = [&](int kt, int b) {
        #pragma unroll
        for (int i = 0; i < 2; i++) {
            int f = tid + i * 256;
            int r = f >> 3, c4 = f & 7;
            int m = m0 + r;
            bool p = m < M;
            const char* src = A + (size_t)(p ? m : 0) * ROWB + kt * 128 + c4 * 16;
            cp16((uint32_t)__cvta_generic_to_shared(As + b * AW + r * SPAD + c4 * 4), src, p);
        }
        #pragma unroll
        for (int i = 0; i < NT / 32; i++) {
            int f = tid + i * 256;
            int r = f >> 3, c4 = f & 7;
            const char* src = Bt + (size_t)(n0 + r) * ROWB + kt * 128 + c4 * 16;
            cp16((uint32_t)__cvta_generic_to_shared(Bs + b * BW + r * SPAD + c4 * 4), src, true);
        }
    };

    issue(0, 0);
    CP_COMMIT();

    for (int kt = 0; kt < KT; kt++) {
        if (kt + 1 < KT) {
            issue(kt + 1, (kt + 1) & 1);
            CP_COMMIT();
            asm volatile("cp.async.wait_group 1;" ::: "memory");
        } else {
            CP_WAIT0();
        }
        __syncthreads();

        int b = kt & 1;
        const uint32_t* Ab = As + b * AW;
        const uint32_t* Bb = Bs + b * BW;
        #pragma unroll
        for (int ks = 0; ks < 4; ks++) {
            int kc = ks * 8 + lr;
            const uint32_t* ap = Ab + (mbase + lq) * SPAD;
            uint32_t a0 = ap[kc];
            uint32_t a1 = ap[8 * SPAD + kc];
            uint32_t a2 = ap[kc + 4];
            uint32_t a3 = ap[8 * SPAD + kc + 4];
            #pragma unroll
            for (int nt = 0; nt < NTI; nt++) {
                const uint32_t* bp = Bb + (nbase + nt * 8 + lq) * SPAD;
                uint32_t b0 = bp[kc];
                uint32_t b1 = bp[kc + 4];
                if (FH) mma_f16(acc[nt], a0, a1, a2, a3, b0, b1);
                else    mma_tf32(acc[nt], a0, a1, a2, a3, b0, b1);
            }
        }
        __syncthreads();
    }

    // epilogue stores
    int r0 = m0 + mbase + lq;
    int r1 = r0 + 8;
    #pragma unroll
    for (int nt = 0; nt < NTI; nt++) {
        int lc = nbase + nt * 8 + lr * 2;   // tile-local col
        int c = n0 + lc;                    // global col
        if (MODE == 0) {
            __half2* Ch = reinterpret_cast<__half2*>(Cout);
            if (r0 < M) Ch[(size_t)r0 * 256 + (c >> 1)] =
                __floats2half2_rn(acc[nt][0], acc[nt][1]);
            if (r1 < M) Ch[(size_t)r1 * 256 + (c >> 1)] =
                __floats2half2_rn(acc[nt][2], acc[nt][3]);
        } else if (MODE == 1) {
            __half2* Ch = reinterpret_cast<__half2*>(Cout);
            if (r0 < M) Ch[(size_t)r0 * 32 + (c >> 1)] =
                __floats2half2_rn(acc[nt][0], acc[nt][1]);
            if (r1 < M) Ch[(size_t)r1 * 32 + (c >> 1)] =
                __floats2half2_rn(acc[nt][2], acc[nt][3]);
        } else if (MODE == 2) {
            __half2* Ch = reinterpret_cast<__half2*>(Cout);
            float bx = s_a[lc], by = s_a[lc + 1];
            if (r0 < M) Ch[(size_t)r0 * 128 + (c >> 1)] =
                __floats2half2_rn(elu1(acc[nt][0] + bx), elu1(acc[nt][1] + by));
            if (r1 < M) Ch[(size_t)r1 * 128 + (c >> 1)] =
                __floats2half2_rn(elu1(acc[nt][2] + bx), elu1(acc[nt][3] + by));
        } else {  // MODE 3
            if (c < NCLASS) {
                float* Cf = reinterpret_cast<float*>(Cout);
                float bx = s_a[c], by = s_a[c + 1];
                if (r0 < M)
                    *reinterpret_cast<float2*>(Cf + (size_t)r0 * NCLASS + c) =
                        make_float2(acc[nt][0] + bx, acc[nt][1] + by);
                if (r1 < M)
                    *reinterpret_cast<float2*>(Cf + (size_t)r1 * NCLASS + c) =
                        make_float2(acc[nt][2] + bx, acc[nt][3] + by);
            }
        }
    }

    // fused attention-vector dots
    if (MODE <= 1) {
        const float* va = (MODE == 0) ? s_a + wn * 128 : s_a;
        float p1a = 0.f, p1b = 0.f, p2a = 0.f, p2b = 0.f;
        #pragma unroll
        for (int nt = 0; nt < NTI; nt++) {
            int o = (MODE == 0) ? (nt * 8 + lr * 2) : (nbase + nt * 8 + lr * 2);
            float a1x = va[o], a1y = va[o + 1];
            float a2x = va[64 + o], a2y = va[64 + o + 1];
            p1a += acc[nt][0] * a1x + acc[nt][1] * a1y;
            p2a += acc[nt][0] * a2x + acc[nt][1] * a2y;
            p1b += acc[nt][2] * a1x + acc[nt][3] * a1y;
            p2b += acc[nt][2] * a2x + acc[nt][3] * a2y;
        }
        p1a += __shfl_xor_sync(0xffffffffu, p1a, 1); p1a += __shfl_xor_sync(0xffffffffu, p1a, 2);
        p1b += __shfl_xor_sync(0xffffffffu, p1b, 1); p1b += __shfl_xor_sync(0xffffffffu, p1b, 2);
        p2a += __shfl_xor_sync(0xffffffffu, p2a, 1); p2a += __shfl_xor_sync(0xffffffffu, p2a, 2);
        p2b += __shfl_xor_sync(0xffffffffu, p2b, 1); p2b += __shfl_xor_sync(0xffffffffu, p2b, 2);
        if (MODE == 0) {
            if (lr == 0) {
                size_t hoff = (size_t)(blockIdx.y * 2 + wn) * NN;
                if (r0 < M) { f1o[hoff + r0] = p1a; f2o[hoff + r0] = p2a; }
                if (r1 < M) { f1o[hoff + r1] = p1b; f2o[hoff + r1] = p2b; }
            }
        } else {
            float* sp1 = s_red;            // [2][64]
            float* sp2 = s_red + 128;      // [2][64]
            if (lr == 0) {
                sp1[wn * 64 + mbase + lq] = p1a;
                sp1[wn * 64 + mbase + lq + 8] = p1b;
                sp2[wn * 64 + mbase + lq] = p2a;
                sp2[wn * 64 + mbase + lq + 8] = p2b;
            }
            __syncthreads();
            if (tid < 64 && m0 + tid < M) {
                f1o[m0 + tid] = sp1[tid] + sp1[64 + tid];
                f2o[m0 + tid] = sp2[tid] + sp2[64 + tid];
            }
        }
    }
}

// ---------------- K3: layer-1 sparse attention + aggregation + elu --------
__global__ void gat_agg1() {
    int n = blockIdx.x;
    __shared__ int   s_idx[MAXDEG];
    __shared__ float s_f2[NHEADS][MAXDEG];
    __shared__ float s_w [NHEADS][MAXDEG];
    int tid = threadIdx.x;
    int deg = d_cnt[n];

    for (int j = tid; j < deg; j += 256) s_idx[j] = d_nbr[n * MAXDEG + j];
    __syncthreads();

    int w = tid >> 5, lane = tid & 31;
    // warp w gathers head w's f2 row (no int division, no extra barrier:
    // only warp w reads s_f2[w])
    for (int j = lane; j < deg; j += 32) s_f2[w][j] = d_f2[w * NN + s_idx[j]];
    __syncwarp();

    float f1v = d_f1[w * NN + n];

    float mx = -1e30f;
    for (int j = lane; j < deg; j += 32) mx = fmaxf(mx, leaky(f1v + s_f2[w][j]));
    #pragma unroll
    for (int off = 16; off; off >>= 1) mx = fmaxf(mx, __shfl_xor_sync(0xffffffffu, mx, off));

    float sum = 0.f;
    for (int j = lane; j < deg; j += 32) {
        float e = expf(leaky(f1v + s_f2[w][j]) - mx);
        s_w[w][j] = e;
        sum += e;
    }
    #pragma unroll
    for (int off = 16; off; off >>= 1) sum += __shfl_xor_sync(0xffffffffu, sum, off);
    __syncwarp();

    float accx = 0.f, accy = 0.f;
    const __half2* whb = d_Whh + w * 32 + lane;
    for (int j = 0; j < deg; j++) {
        float wj = s_w[w][j];
        float2 v = __half22float2(whb[(size_t)s_idx[j] * 256]);
        accx += wj * v.x;
        accy += wj * v.y;
    }
    float inv = 1.f / sum;
    d_h1h[(size_t)n * 256 + w * 32 + lane] =
        __floats2half2_rn(elu1(accx * inv), elu1(accy * inv));
}

// ---------------- K6: layer-2 attention + aggregation (h2 only) -----------
__global__ void gat_agg2() {
    int n = blockIdx.x;
    __shared__ int   s_idx[MAXDEG];
    __shared__ float s_g2[MAXDEG];
    __shared__ float s_w [MAXDEG];
    __shared__ float s_sum;
    __shared__ float2 s_part[8][32];
    int tid = threadIdx.x;
    int deg = d_cnt[n];

    for (int j = tid; j < deg; j += 256) {
        int c = d_nbr[n * MAXDEG + j];
        s_idx[j] = c;
        s_g2[j]  = d_g2[c];
    }
    __syncthreads();

    if (tid < 32) {
        float g1n = d_g1[n];
        float mx = -1e30f;
        for (int j = tid; j < deg; j += 32) mx = fmaxf(mx, leaky(g1n + s_g2[j]));
        #pragma unroll
        for (int off = 16; off; off >>= 1) mx = fmaxf(mx, __shfl_xor_sync(0xffffffffu, mx, off));
        float sum = 0.f;
        for (int j = tid; j < deg; j += 32) {
            float e = expf(leaky(g1n + s_g2[j]) - mx);
            s_w[j] = e;
            sum += e;
        }
        #pragma unroll
        for (int off = 16; off; off >>= 1) sum += __shfl_xor_sync(0xffffffffu, sum, off);
        if (tid == 0) s_sum = sum;
    }
    __syncthreads();

    {
        int o2 = tid & 31, part = tid >> 5;
        float ax = 0.f, ay = 0.f;
        for (int j = part; j < deg; j += 8) {
            float wj = s_w[j];
            float2 v = __half22float2(d_Wh2h[(size_t)s_idx[j] * 32 + o2]);
            ax += wj * v.x;
            ay += wj * v.y;
        }
        s_part[part][o2] = make_float2(ax, ay);
    }
    __syncthreads();
    if (tid < 32) {
        float ax = 0.f, ay = 0.f;
        #pragma unroll
        for (int p = 0; p < 8; p++) {
            float2 v = s_part[p][tid];
            ax += v.x;
            ay += v.y;
        }
        float inv = 1.f / s_sum;
        d_h2[(size_t)n * 64 + 2 * tid]     = __uint_as_float(f2tf32(ax * inv));
        d_h2[(size_t)n * 64 + 2 * tid + 1] = __uint_as_float(f2tf32(ay * inv));
    }
}

// ---------------- launch ----------------------------------------------------
extern "C" void kernel_launch(void* const* d_in, const int* in_sizes, int n_in,
                              void* d_out, int out_size) {
    const float* x     = (const float*)d_in[0];
    const float* adj   = (const float*)d_in[1];
    const float* W_h   = (const float*)d_in[2];
    const float* a_h   = (const float*)d_in[3];
    const float* W_o   = (const float*)d_in[4];
    const float* a_o   = (const float*)d_in[5];
    const float* fc1_w = (const float*)d_in[6];
    const float* fc1_b = (const float*)d_in[7];
    const float* fc2_w = (const float*)d_in[8];
    const float* fc2_b = (const float*)d_in[9];
    float* out = (float*)d_out;

    void *pWhh, *pH1h, *pXh, *pWh2h, *pH2, *pH3h, *pBt1h, *pBt2h, *pBt3, *pBt4h;
    void *pB3, *pB4, *pF1, *pF2, *pG1, *pG2;
    cudaGetSymbolAddress(&pWhh,   d_Whh);
    cudaGetSymbolAddress(&pH1h,   d_h1h);
    cudaGetSymbolAddress(&pXh,    d_xh);
    cudaGetSymbolAddress(&pWh2h,  d_Wh2h);
    cudaGetSymbolAddress(&pH2,    d_h2);
    cudaGetSymbolAddress(&pH3h,   d_h3h);
    cudaGetSymbolAddress(&pBt1h,  d_Bt1h);
    cudaGetSymbolAddress(&pBt2h,  d_Bt2h);
    cudaGetSymbolAddress(&pBt3,   d_Bt3);
    cudaGetSymbolAddress(&pBt4h,  d_Bt4h);
    cudaGetSymbolAddress(&pB3,    d_bias3);
    cudaGetSymbolAddress(&pB4,    d_bias4);
    cudaGetSymbolAddress(&pF1,    d_f1);
    cudaGetSymbolAddress(&pF2,    d_f2);
    cudaGetSymbolAddress(&pG1,    d_g1);
    cudaGetSymbolAddress(&pG2,    d_g2);

    const int MB = (NN + 63) / 64;   // 79
    const int SM_M0 = (256 + 256 + (2 * 64 + 2 * 128) * SPAD) * 4;
    const int SM_M1 = (128 + 256 + (2 * 64 + 2 * 64) * SPAD) * 4;
    const int SM_M2 = (128 + 256 + (2 * 64 + 2 * 128) * SPAD) * 4;
    const int SM_M3 = (64 + 256 + (2 * 64 + 2 * 64) * SPAD) * 4;
    cudaFuncSetAttribute(gat_mma_gemm<128, 8, 0, 1>, cudaFuncAttributeMaxDynamicSharedMemorySize, SM_M0);
    cudaFuncSetAttribute(gat_mma_gemm<64, 8, 1, 1>,  cudaFuncAttributeMaxDynamicSharedMemorySize, SM_M1);
    cudaFuncSetAttribute(gat_mma_gemm<128, 2, 2, 0>, cudaFuncAttributeMaxDynamicSharedMemorySize, SM_M2);
    cudaFuncSetAttribute(gat_mma_gemm<64, 4, 3, 1>,  cudaFuncAttributeMaxDynamicSharedMemorySize, SM_M3);

    cudaStream_t s2;
    cudaStreamCreateWithFlags(&s2, cudaStreamNonBlocking);
    cudaEvent_t e0, e1;
    cudaEventCreateWithFlags(&e0, cudaEventDisableTiming);
    cudaEventCreateWithFlags(&e1, cudaEventDisableTiming);

    cudaEventRecord(e0, 0);
    cudaStreamWaitEvent(s2, e0, 0);
    gat_build_csr<<<NN, 256, 0, s2>>>(adj);
    cudaEventRecord(e1, s2);

    gat_prep<<<PREP_BLOCKS, 256>>>(x, W_h, W_o, fc1_w, fc1_b, fc2_w, fc2_b);
    gat_mma_gemm<128, 8, 0, 1><<<dim3(MB, 4), 256, SM_M0>>>((const char*)pXh,
        (const char*)pBt1h, pWhh, NN, a_h, (float*)pF1, (float*)pF2);
    cudaStreamWaitEvent(0, e1, 0);
    gat_agg1<<<NN, 256>>>();
    gat_mma_gemm<64, 8, 1, 1><<<dim3(MB, 1), 256, SM_M1>>>((const char*)pH1h,
        (const char*)pBt2h, pWh2h, NN, a_o, (float*)pG1, (float*)pG2);
    gat_agg2<<<NN, 256>>>();
    gat_mma_gemm<128, 2, 2, 0><<<dim3(MB, 2), 256, SM_M2>>>((const char*)pH2,
        (const char*)pBt3, pH3h, NN, (const float*)pB3, nullptr, nullptr);
    gat_mma_gemm<64, 4, 3, 1><<<dim3(MB, 1), 256, SM_M3>>>((const char*)pH3h,
        (const char*)pBt4h, out, NN, (const float*)pB4, nullptr, nullptr);

    cudaEventDestroy(e0);
    cudaEventDestroy(e1);
    cudaStreamDestroy(s2);
}